// round 16
// baseline (speedup 1.0000x reference)
#include <cuda_runtime.h>
#include <cuda_fp16.h>
#include <cstdint>

// Problem constants
#define BATCH   16384
#define NCLS    1000
#define NPAD    1024
#define KDIM    1024

// GEMM tiling (fp16): CTA 128x128, 8 warps 4(M)x2(N), 3-stage cp.async ring
#define BM 128
#define BN 128
#define BKH 64               // halves per k-chunk (128 bytes per smem row)
#define KT (KDIM / BKH)      // 16 k-chunks
#define NT 8                 // 8 * 128 = 1024 >= 1000
#define SLD 36               // smem row stride in uint32 (32 data + 4 pad)
#define NSTG 3
#define STG_U32 ((BM + BN) * SLD)      // u32 per stage (A then B)
#define MB (BATCH / BM)                 // 128 x-tiles in M
#define GRIDY (MB + NPAD / BM)          // 136 (last 8 rows = centers self-GEMM)

// conv grid: 1024 x-blocks (256 thr x 16 float4 each) + 1000 center blocks
#define XCONV_BLKS 1024

// ---------------------------------------------------------------------------
// Scratch (zero-initialized; pad rows of g_ch stay zero forever)
// ---------------------------------------------------------------------------
__device__ __half g_xh[(size_t)BATCH * KDIM];    // fp16 x
__device__ __half g_ch[(size_t)NPAD * KDIM];     // fp16 centers, rows 1000..1023 zero
__device__ float  g_c2[NPAD];                    // exact fp32 ||c||^2
__device__ float  g_pos[BATCH];
__device__ float  g_minxc[(size_t)BATCH * NT];
__device__ float  g_mincc[(size_t)NPAD * NT];
__device__ float  g_part[64];
__device__ int    g_ticket;                      // last-block detector (self-resetting)

// ---------------------------------------------------------------------------
// Prep: fused x conversion (MLP16, fused stores) + center conv/norm
// ---------------------------------------------------------------------------
__device__ __forceinline__ uint2 cvt4(float4 v) {
    __half2 lo = __floats2half2_rn(v.x, v.y);
    __half2 hi = __floats2half2_rn(v.z, v.w);
    uint2 o;
    o.x = *reinterpret_cast<uint32_t*>(&lo);
    o.y = *reinterpret_cast<uint32_t*>(&hi);
    return o;
}

__global__ void conv_all_kernel(const float* __restrict__ x,
                                const float* __restrict__ centers) {
    int blk = blockIdx.x;
    if (blk < XCONV_BLKS) {
        // x: 16 float4 per thread in 2 batches of 8 front-batched loads;
        // two float4 -> one uint4 store (halves STG count).
        const float4* xs = reinterpret_cast<const float4*>(x);
        uint4* xd = reinterpret_cast<uint4*>(g_xh);
#pragma unroll
        for (int half = 0; half < 2; half++) {
            // input float4 index: blk owns [blk*4096, blk*4096+4096)
            int ibase = blk * 4096 + half * 2048 + threadIdx.x;
            float4 v[8];
#pragma unroll
            for (int i = 0; i < 8; i++)
                v[i] = xs[ibase + i * 256];
            // output uint4 index: pair consecutive float4 batches (i, i+1):
            // batches i and i+1 are 256 apart in float4 space = 128 apart in
            // uint4 space; store uint4 at (ibase>>1 rounded) — recompute:
            // float4 j maps to halves 4j..4j+3 -> uint4 index j/2, lane j&1.
            int obase = (blk * 4096 + half * 2048) >> 1;   // uint4 units
#pragma unroll
            for (int i = 0; i < 4; i++) {
                uint2 lo = cvt4(v[2 * i]);         // float4 index ibase+2i*256
                uint2 hi = cvt4(v[2 * i + 1]);     // float4 index ibase+(2i+1)*256
                // float4 f = ibase + k*256 -> uint4 idx = f>>1, half sel f&1.
                // ibase+2i*256 and ibase+(2i+1)*256 differ by 256 (even), so
                // they are DIFFERENT uint4s unless paired correctly. Pair the
                // two halves of the SAME uint4 instead: f and f+1 share idx
                // only when f is even... use direct mapping: thread stores
                // uint4 for float4 pair (2*(ibase>>1)+... ) — simpler: store
                // each cvt4 as its own uint2 (fallback to correctness).
                reinterpret_cast<uint2*>(xd)[ibase + 2 * i * 256] = lo;
                reinterpret_cast<uint2*>(xd)[ibase + (2 * i + 1) * 256] = hi;
            }
        }
    } else {
        // center row conversion + exact fp32 norm
        int j = blk - XCONV_BLKS;       // class 0..999
        const float* row = centers + (size_t)j * KDIM;
        float acc = 0.f;
        for (int k4 = threadIdx.x; k4 < KDIM / 4; k4 += 256) {
            float4 v = reinterpret_cast<const float4*>(row)[k4];
            acc += v.x * v.x + v.y * v.y + v.z * v.z + v.w * v.w;
            reinterpret_cast<uint2*>(g_ch + (size_t)j * KDIM)[k4] = cvt4(v);
        }
        __shared__ float s[256];
        s[threadIdx.x] = acc;
        __syncthreads();
        for (int off = 128; off > 0; off >>= 1) {
            if (threadIdx.x < off) s[threadIdx.x] += s[threadIdx.x + off];
            __syncthreads();
        }
        if (threadIdx.x == 0) g_c2[j] = s[0];
    }
}

// ---------------------------------------------------------------------------
// fp16 GEMM + fused min epilogue (merged: grid.y < MB -> x rows, else centers)
// e[r,c] = 0.5*||c_c||^2 - dot(A_r, C_c)   — byte-identical to round 15
// ---------------------------------------------------------------------------
__device__ __forceinline__ void cp_tile(const __half* gbase, uint32_t* sbase, int tid) {
#pragma unroll
    for (int i = 0; i < 4; i++) {
        int g = i * 256 + tid;          // 0..1023 chunk id
        int r = g >> 3;                 // row 0..127
        int q = g & 7;                  // 16B chunk within row
        uint32_t d = (uint32_t)__cvta_generic_to_shared(sbase + r * SLD + q * 4);
        const __half* s = gbase + (size_t)r * KDIM + q * 8;
        asm volatile("cp.async.cg.shared.global [%0], [%1], 16;" :: "r"(d), "l"(s));
    }
}

__device__ __forceinline__ void ldsm4(uint32_t& r0, uint32_t& r1, uint32_t& r2,
                                      uint32_t& r3, uint32_t addr) {
    asm volatile("ldmatrix.sync.aligned.m8n8.x4.shared.b16 {%0,%1,%2,%3}, [%4];"
                 : "=r"(r0), "=r"(r1), "=r"(r2), "=r"(r3) : "r"(addr));
}

#define HMMA(acc, a, b0, b1)                                                   \
    asm volatile(                                                              \
        "mma.sync.aligned.m16n8k16.row.col.f32.f16.f16.f32 "                   \
        "{%0,%1,%2,%3}, {%4,%5,%6,%7}, {%8,%9}, {%0,%1,%2,%3};"                \
        : "+f"((acc)[0]), "+f"((acc)[1]), "+f"((acc)[2]), "+f"((acc)[3])       \
        : "r"((a)[0]), "r"((a)[1]), "r"((a)[2]), "r"((a)[3]), "r"(b0), "r"(b1))

__global__ void __launch_bounds__(256, 2)
gemm_min_kernel(const int* __restrict__ labels) {
    extern __shared__ uint32_t smem[];
    float* c2s  = (float*)(smem + NSTG * STG_U32);   // 128 floats (pre-scaled by 0.5)
    float* red  = c2s + 128;                         // 128 * 2 floats
    int*   labs = (int*)(red + 256);                 // 128 ints

    const int tid  = threadIdx.x;
    const int warp = tid >> 5;
    const int lane = tid & 31;
    const int wm   = warp >> 1;   // 0..3  (M warps, 32 rows each)
    const int wn   = warp & 1;    // 0..1  (N warps, 64 cols each)
    const int bx   = blockIdx.x;  // n-tile 0..7
    const int by   = blockIdx.y;
    const bool self = by >= MB;            // uniform per block
    const int m0   = (self ? (by - MB) : by) * BM;
    const int n0   = bx * BN;

    if (tid < 128) {
        c2s[tid] = 0.5f * g_c2[n0 + tid];
        if (!self) labs[tid] = labels[m0 + tid];
    }

    float acc[2][8][4];
#pragma unroll
    for (int mi = 0; mi < 2; mi++)
#pragma unroll
        for (int ni = 0; ni < 8; ni++)
#pragma unroll
            for (int r = 0; r < 4; r++) acc[mi][ni][r] = 0.f;

    const __half* Abase = (self ? g_ch : g_xh) + (size_t)m0 * KDIM;
    const __half* Bbase = g_ch + (size_t)n0 * KDIM;

    // ldmatrix per-lane base addresses (byte units, offsets within a stage)
    const uint32_t smb = (uint32_t)__cvta_generic_to_shared(smem);
    const int rowA  = (lane & 7) + ((lane >> 3) & 1) * 8;
    const int koffA = (lane >> 4) * 4;                 // u32 units
    const int rowB  = (lane & 7) + ((lane >> 4) & 1) * 8;
    const int koffB = ((lane >> 3) & 1) * 4;           // u32 units

    uint32_t aAddr[2], bAddr[4];
#pragma unroll
    for (int mi = 0; mi < 2; mi++)
        aAddr[mi] = smb + 4u * ((wm * 32 + mi * 16 + rowA) * SLD + koffA);
#pragma unroll
    for (int pi = 0; pi < 4; pi++)
        bAddr[pi] = smb + 4u * (BM * SLD + (wn * 64 + pi * 16 + rowB) * SLD + koffB);

    // prologue: stages 0, 1 (chunks 0, 1)
#pragma unroll
    for (int s = 0; s < 2; s++) {
        uint32_t* st = smem + s * STG_U32;
        cp_tile(Abase + (size_t)s * BKH, st, tid);
        cp_tile(Bbase + (size_t)s * BKH, st + BM * SLD, tid);
        asm volatile("cp.async.commit_group;");
    }

    const int lr = lane >> 2, lc = lane & 3;

    for (int kt = 0; kt < KT; kt++) {
        // 1) own-thread completion of chunk kt (pending = {kt, kt+1})
        if (kt + 1 < KT) asm volatile("cp.async.wait_group 1;");
        else             asm volatile("cp.async.wait_group 0;");
        // 2) publish chunk kt to ALL threads; also: all warps done with iter
        //    kt-1, so refilling stage (kt+2)%3 (consumed at kt-1) is safe
        __syncthreads();
        // 3) refill
        if (kt + 2 < KT) {
            uint32_t* st = smem + ((kt + 2) % NSTG) * STG_U32;
            cp_tile(Abase + (size_t)(kt + 2) * BKH, st, tid);
            cp_tile(Bbase + (size_t)(kt + 2) * BKH, st + BM * SLD, tid);
            asm volatile("cp.async.commit_group;");
        }
        // 4) compute chunk kt from stage kt%3 — software-pipelined kk loop
        const uint32_t sOff = (uint32_t)((kt % NSTG) * STG_U32 * 4);

        uint32_t af[2][2][4];   // ping-pong A fragments across kk
#pragma unroll
        for (int mi = 0; mi < 2; mi++)
            ldsm4(af[0][mi][0], af[0][mi][1], af[0][mi][2], af[0][mi][3],
                  aAddr[mi] + sOff);

#pragma unroll
        for (int kk = 0; kk < 4; kk++) {
            const int cur = kk & 1, nxt = cur ^ 1;
            uint32_t bf[8][2];
            // B first half: ni 0..3
#pragma unroll
            for (int pi = 0; pi < 2; pi++)
                ldsm4(bf[2 * pi][0], bf[2 * pi][1], bf[2 * pi + 1][0], bf[2 * pi + 1][1],
                      bAddr[pi] + sOff + kk * 32);
            // prefetch A for kk+1 (hidden under first-half HMMAs)
            if (kk < 3) {
#pragma unroll
                for (int mi = 0; mi < 2; mi++)
                    ldsm4(af[nxt][mi][0], af[nxt][mi][1], af[nxt][mi][2], af[nxt][mi][3],
                          aAddr[mi] + sOff + (kk + 1) * 32);
            }
#pragma unroll
            for (int mi = 0; mi < 2; mi++)
#pragma unroll
                for (int ni = 0; ni < 4; ni++)
                    HMMA(acc[mi][ni], af[cur][mi], bf[ni][0], bf[ni][1]);
            // B second half: ni 4..7 (latency hidden by the 8 HMMAs above)
#pragma unroll
            for (int pi = 2; pi < 4; pi++)
                ldsm4(bf[2 * pi][0], bf[2 * pi][1], bf[2 * pi + 1][0], bf[2 * pi + 1][1],
                      bAddr[pi] + sOff + kk * 32);
#pragma unroll
            for (int mi = 0; mi < 2; mi++)
#pragma unroll
                for (int ni = 4; ni < 8; ni++)
                    HMMA(acc[mi][ni], af[cur][mi], bf[ni][0], bf[ni][1]);
        }
    }
    __syncthreads();   // all warps done with last stage before red[] reuse

    // ---------------- fused epilogue ----------------
    const float INF = __int_as_float(0x7f800000);
    float rmin[2][2];

#pragma unroll
    for (int mi = 0; mi < 2; mi++)
#pragma unroll
        for (int h = 0; h < 2; h++) {
            int rloc = wm * 32 + mi * 16 + lr + 8 * h;
            float rm = INF;
#pragma unroll
            for (int ni = 0; ni < 8; ni++)
#pragma unroll
                for (int cc = 0; cc < 2; cc++) {
                    int cloc = wn * 64 + ni * 8 + lc * 2 + cc;
                    float e = c2s[cloc] - acc[mi][ni][h * 2 + cc];
                    int cg = n0 + cloc;
                    bool excl = (cg >= NCLS);
                    if (self) {
                        excl = excl || (cg == m0 + rloc);
                    } else if (cg == labs[rloc]) {
                        g_pos[m0 + rloc] = e;
                        excl = true;
                    }
                    if (!excl) rm = fminf(rm, e);
                }
            rmin[mi][h] = rm;
        }

#pragma unroll
    for (int mi = 0; mi < 2; mi++)
#pragma unroll
        for (int h = 0; h < 2; h++) {
            float v = rmin[mi][h];
            v = fminf(v, __shfl_xor_sync(0xffffffffu, v, 1));
            v = fminf(v, __shfl_xor_sync(0xffffffffu, v, 2));
            rmin[mi][h] = v;
        }

    if (lc == 0) {
#pragma unroll
        for (int mi = 0; mi < 2; mi++)
#pragma unroll
            for (int h = 0; h < 2; h++) {
                int rloc = wm * 32 + mi * 16 + lr + 8 * h;
                red[rloc * 2 + wn] = rmin[mi][h];
            }
    }
    __syncthreads();

    if (tid < 128) {
        float v = fminf(red[tid * 2], red[tid * 2 + 1]);
        int rg = m0 + tid;
        if (self) {
            if (rg < NCLS) g_mincc[(size_t)rg * NT + bx] = v;
        } else {
            g_minxc[(size_t)rg * NT + bx] = v;
        }
    }
}

// ---------------------------------------------------------------------------
// Deterministic reduction: 64 blocks; LAST block (ticket) does the final sum
// of the 64 partials in fixed order and resets the ticket for graph replays.
// ---------------------------------------------------------------------------
__global__ void partial_kernel(const int* __restrict__ labels, float* __restrict__ out) {
    int b = blockIdx.x * 256 + threadIdx.x;
    float4 a = reinterpret_cast<const float4*>(g_minxc)[b * 2];
    float4 c = reinterpret_cast<const float4*>(g_minxc)[b * 2 + 1];
    float m = fminf(fminf(fminf(a.x, a.y), fminf(a.z, a.w)),
                    fminf(fminf(c.x, c.y), fminf(c.z, c.w)));
    int lab = labels[b];
    float4 d = reinterpret_cast<const float4*>(g_mincc)[lab * 2];
    float4 e = reinterpret_cast<const float4*>(g_mincc)[lab * 2 + 1];
    float mc = fminf(fminf(fminf(d.x, d.y), fminf(d.z, d.w)),
                     fminf(fminf(e.x, e.y), fminf(e.z, e.w)));
    float t1 = g_pos[b] + 5.0f - m;              // 0.5||x||^2 cancels in pos - neg
    float t2 = 7.0f - (0.5f * g_c2[lab] + mc);   // cen fused
    float v = fmaxf(t1, 0.f) + fmaxf(t2, 0.f);
#pragma unroll
    for (int off = 16; off > 0; off >>= 1)
        v += __shfl_xor_sync(0xffffffffu, v, off);
    __shared__ float s[8];
    __shared__ bool last;
    if ((threadIdx.x & 31) == 0) s[threadIdx.x >> 5] = v;
    __syncthreads();
    if (threadIdx.x == 0) {
        float t = s[0];
#pragma unroll
        for (int w = 1; w < 8; w++) t += s[w];
        g_part[blockIdx.x] = t;
        __threadfence();                          // publish partial before ticket
        last = (atomicAdd(&g_ticket, 1) == 63);
    }
    __syncthreads();
    if (last && threadIdx.x == 0) {
        __threadfence();                          // acquire all partials
        float t = 0.f;
#pragma unroll
        for (int w = 0; w < 64; w++) t += g_part[w];   // fixed order: deterministic
        out[0] = t * (1.0f / (float)BATCH);
        g_ticket = 0;                              // reset for next graph replay
    }
}

// ---------------------------------------------------------------------------
// Launch
// ---------------------------------------------------------------------------
extern "C" void kernel_launch(void* const* d_in, const int* in_sizes, int n_in,
                              void* d_out, int out_size) {
    const float* x       = (const float*)d_in[0];
    const int*   labels  = (const int*)d_in[1];
    const float* centers = (const float*)d_in[2];
    float* out = (float*)d_out;

    const int smem_bytes = (NSTG * STG_U32 + 128 + 256 + 128) * 4;   // 112640
    cudaFuncSetAttribute(gemm_min_kernel,
                         cudaFuncAttributeMaxDynamicSharedMemorySize, smem_bytes);

    // fused prep: x conversion (blocks 0..1023, 16 float4/thread) + centers
    conv_all_kernel<<<XCONV_BLKS + NCLS, 256>>>(x, centers);

    // merged GEMM: x vs centers (grid.y < 128) + centers vs centers (grid.y >= 128)
    gemm_min_kernel<<<dim3(NT, GRIDY), 256, smem_bytes>>>(labels);

    // single reduction launch (finish fused via ticket)
    partial_kernel<<<64, 256>>>(labels, out);
}

// round 17
// speedup vs baseline: 1.0111x; 1.0111x over previous
#include <cuda_runtime.h>
#include <cuda_fp16.h>
#include <cstdint>

// Problem constants
#define BATCH   16384
#define NCLS    1000
#define NPAD    1024
#define KDIM    1024

// GEMM tiling (fp16): CTA 128x128, 8 warps 4(M)x2(N), 3-stage cp.async ring
#define BM 128
#define BN 128
#define BKH 64               // halves per k-chunk (128 bytes per smem row)
#define KT (KDIM / BKH)      // 16 k-chunks
#define NT 8                 // 8 * 128 = 1024 >= 1000
#define SLD 36               // smem row stride in uint32 (32 data + 4 pad)
#define NSTG 3
#define STG_U32 ((BM + BN) * SLD)      // u32 per stage (A then B)
#define MB (BATCH / BM)                 // 128 x-tiles in M
#define GRIDY (MB + NPAD / BM)          // 136 (last 8 rows = centers self-GEMM)

// conv grid: 2048 x-blocks (256 thr x 8 float4 each) + 1000 center blocks
#define XCONV_BLKS 2048
#define XCONV_PER_THREAD 8              // float4s per thread (MLP)

// ---------------------------------------------------------------------------
// Scratch (zero-initialized; pad rows of g_ch stay zero forever)
// ---------------------------------------------------------------------------
__device__ __half g_xh[(size_t)BATCH * KDIM];    // fp16 x
__device__ __half g_ch[(size_t)NPAD * KDIM];     // fp16 centers, rows 1000..1023 zero
__device__ float  g_c2[NPAD];                    // exact fp32 ||c||^2
__device__ float  g_pos[BATCH];
__device__ float  g_minxc[(size_t)BATCH * NT];
__device__ float  g_mincc[(size_t)NPAD * NT];
__device__ float  g_part[64];
__device__ int    g_ticket;                      // last-block detector (self-resetting)

// ---------------------------------------------------------------------------
// Prep: fused x conversion (MLP=8, evict-first reads) + center conv/norm
// ---------------------------------------------------------------------------
__device__ __forceinline__ uint2 cvt4(float4 v) {
    __half2 lo = __floats2half2_rn(v.x, v.y);
    __half2 hi = __floats2half2_rn(v.z, v.w);
    uint2 o;
    o.x = *reinterpret_cast<uint32_t*>(&lo);
    o.y = *reinterpret_cast<uint32_t*>(&hi);
    return o;
}

__global__ void conv_all_kernel(const float* __restrict__ x,
                                const float* __restrict__ centers) {
    int blk = blockIdx.x;
    if (blk < XCONV_BLKS) {
        // x conversion: 8 float4s per thread, front-batched loads (MLP=8).
        // __ldcs: x fp32 is dead after this kernel -> evict-first, keep L2
        // owned by the fp16 outputs the GEMM is about to stream.
        const float4* xs = reinterpret_cast<const float4*>(x);
        uint2* xd = reinterpret_cast<uint2*>(g_xh);
        int base = blk * (256 * XCONV_PER_THREAD) + threadIdx.x;
        float4 v[XCONV_PER_THREAD];
#pragma unroll
        for (int i = 0; i < XCONV_PER_THREAD; i++)
            v[i] = __ldcs(&xs[base + i * 256]);
#pragma unroll
        for (int i = 0; i < XCONV_PER_THREAD; i++)
            xd[base + i * 256] = cvt4(v[i]);
    } else {
        // center row conversion + exact fp32 norm
        int j = blk - XCONV_BLKS;       // class 0..999
        const float* row = centers + (size_t)j * KDIM;
        float acc = 0.f;
        for (int k4 = threadIdx.x; k4 < KDIM / 4; k4 += 256) {
            float4 v = __ldcs(&reinterpret_cast<const float4*>(row)[k4]);
            acc += v.x * v.x + v.y * v.y + v.z * v.z + v.w * v.w;
            reinterpret_cast<uint2*>(g_ch + (size_t)j * KDIM)[k4] = cvt4(v);
        }
        __shared__ float s[256];
        s[threadIdx.x] = acc;
        __syncthreads();
        for (int off = 128; off > 0; off >>= 1) {
            if (threadIdx.x < off) s[threadIdx.x] += s[threadIdx.x + off];
            __syncthreads();
        }
        if (threadIdx.x == 0) g_c2[j] = s[0];
    }
}

// ---------------------------------------------------------------------------
// fp16 GEMM + fused min epilogue (merged: grid.y < MB -> x rows, else centers)
// e[r,c] = 0.5*||c_c||^2 - dot(A_r, C_c)   — byte-identical to round 15
// ---------------------------------------------------------------------------
__device__ __forceinline__ void cp_tile(const __half* gbase, uint32_t* sbase, int tid) {
#pragma unroll
    for (int i = 0; i < 4; i++) {
        int g = i * 256 + tid;          // 0..1023 chunk id
        int r = g >> 3;                 // row 0..127
        int q = g & 7;                  // 16B chunk within row
        uint32_t d = (uint32_t)__cvta_generic_to_shared(sbase + r * SLD + q * 4);
        const __half* s = gbase + (size_t)r * KDIM + q * 8;
        asm volatile("cp.async.cg.shared.global [%0], [%1], 16;" :: "r"(d), "l"(s));
    }
}

__device__ __forceinline__ void ldsm4(uint32_t& r0, uint32_t& r1, uint32_t& r2,
                                      uint32_t& r3, uint32_t addr) {
    asm volatile("ldmatrix.sync.aligned.m8n8.x4.shared.b16 {%0,%1,%2,%3}, [%4];"
                 : "=r"(r0), "=r"(r1), "=r"(r2), "=r"(r3) : "r"(addr));
}

#define HMMA(acc, a, b0, b1)                                                   \
    asm volatile(                                                              \
        "mma.sync.aligned.m16n8k16.row.col.f32.f16.f16.f32 "                   \
        "{%0,%1,%2,%3}, {%4,%5,%6,%7}, {%8,%9}, {%0,%1,%2,%3};"                \
        : "+f"((acc)[0]), "+f"((acc)[1]), "+f"((acc)[2]), "+f"((acc)[3])       \
        : "r"((a)[0]), "r"((a)[1]), "r"((a)[2]), "r"((a)[3]), "r"(b0), "r"(b1))

__global__ void __launch_bounds__(256, 2)
gemm_min_kernel(const int* __restrict__ labels) {
    extern __shared__ uint32_t smem[];
    float* c2s  = (float*)(smem + NSTG * STG_U32);   // 128 floats (pre-scaled by 0.5)
    float* red  = c2s + 128;                         // 128 * 2 floats
    int*   labs = (int*)(red + 256);                 // 128 ints

    const int tid  = threadIdx.x;
    const int warp = tid >> 5;
    const int lane = tid & 31;
    const int wm   = warp >> 1;   // 0..3  (M warps, 32 rows each)
    const int wn   = warp & 1;    // 0..1  (N warps, 64 cols each)
    const int bx   = blockIdx.x;  // n-tile 0..7
    const int by   = blockIdx.y;
    const bool self = by >= MB;            // uniform per block
    const int m0   = (self ? (by - MB) : by) * BM;
    const int n0   = bx * BN;

    if (tid < 128) {
        c2s[tid] = 0.5f * g_c2[n0 + tid];
        if (!self) labs[tid] = labels[m0 + tid];
    }

    float acc[2][8][4];
#pragma unroll
    for (int mi = 0; mi < 2; mi++)
#pragma unroll
        for (int ni = 0; ni < 8; ni++)
#pragma unroll
            for (int r = 0; r < 4; r++) acc[mi][ni][r] = 0.f;

    const __half* Abase = (self ? g_ch : g_xh) + (size_t)m0 * KDIM;
    const __half* Bbase = g_ch + (size_t)n0 * KDIM;

    // ldmatrix per-lane base addresses (byte units, offsets within a stage)
    const uint32_t smb = (uint32_t)__cvta_generic_to_shared(smem);
    const int rowA  = (lane & 7) + ((lane >> 3) & 1) * 8;
    const int koffA = (lane >> 4) * 4;                 // u32 units
    const int rowB  = (lane & 7) + ((lane >> 4) & 1) * 8;
    const int koffB = ((lane >> 3) & 1) * 4;           // u32 units

    uint32_t aAddr[2], bAddr[4];
#pragma unroll
    for (int mi = 0; mi < 2; mi++)
        aAddr[mi] = smb + 4u * ((wm * 32 + mi * 16 + rowA) * SLD + koffA);
#pragma unroll
    for (int pi = 0; pi < 4; pi++)
        bAddr[pi] = smb + 4u * (BM * SLD + (wn * 64 + pi * 16 + rowB) * SLD + koffB);

    // prologue: stages 0, 1 (chunks 0, 1)
#pragma unroll
    for (int s = 0; s < 2; s++) {
        uint32_t* st = smem + s * STG_U32;
        cp_tile(Abase + (size_t)s * BKH, st, tid);
        cp_tile(Bbase + (size_t)s * BKH, st + BM * SLD, tid);
        asm volatile("cp.async.commit_group;");
    }

    const int lr = lane >> 2, lc = lane & 3;

    for (int kt = 0; kt < KT; kt++) {
        // 1) own-thread completion of chunk kt (pending = {kt, kt+1})
        if (kt + 1 < KT) asm volatile("cp.async.wait_group 1;");
        else             asm volatile("cp.async.wait_group 0;");
        // 2) publish chunk kt to ALL threads; also: all warps done with iter
        //    kt-1, so refilling stage (kt+2)%3 (consumed at kt-1) is safe
        __syncthreads();
        // 3) refill
        if (kt + 2 < KT) {
            uint32_t* st = smem + ((kt + 2) % NSTG) * STG_U32;
            cp_tile(Abase + (size_t)(kt + 2) * BKH, st, tid);
            cp_tile(Bbase + (size_t)(kt + 2) * BKH, st + BM * SLD, tid);
            asm volatile("cp.async.commit_group;");
        }
        // 4) compute chunk kt from stage kt%3 — software-pipelined kk loop
        const uint32_t sOff = (uint32_t)((kt % NSTG) * STG_U32 * 4);

        uint32_t af[2][2][4];   // ping-pong A fragments across kk
#pragma unroll
        for (int mi = 0; mi < 2; mi++)
            ldsm4(af[0][mi][0], af[0][mi][1], af[0][mi][2], af[0][mi][3],
                  aAddr[mi] + sOff);

#pragma unroll
        for (int kk = 0; kk < 4; kk++) {
            const int cur = kk & 1, nxt = cur ^ 1;
            uint32_t bf[8][2];
            // B first half: ni 0..3
#pragma unroll
            for (int pi = 0; pi < 2; pi++)
                ldsm4(bf[2 * pi][0], bf[2 * pi][1], bf[2 * pi + 1][0], bf[2 * pi + 1][1],
                      bAddr[pi] + sOff + kk * 32);
            // prefetch A for kk+1 (hidden under first-half HMMAs)
            if (kk < 3) {
#pragma unroll
                for (int mi = 0; mi < 2; mi++)
                    ldsm4(af[nxt][mi][0], af[nxt][mi][1], af[nxt][mi][2], af[nxt][mi][3],
                          aAddr[mi] + sOff + (kk + 1) * 32);
            }
#pragma unroll
            for (int mi = 0; mi < 2; mi++)
#pragma unroll
                for (int ni = 0; ni < 4; ni++)
                    HMMA(acc[mi][ni], af[cur][mi], bf[ni][0], bf[ni][1]);
            // B second half: ni 4..7 (latency hidden by the 8 HMMAs above)
#pragma unroll
            for (int pi = 2; pi < 4; pi++)
                ldsm4(bf[2 * pi][0], bf[2 * pi][1], bf[2 * pi + 1][0], bf[2 * pi + 1][1],
                      bAddr[pi] + sOff + kk * 32);
#pragma unroll
            for (int mi = 0; mi < 2; mi++)
#pragma unroll
                for (int ni = 4; ni < 8; ni++)
                    HMMA(acc[mi][ni], af[cur][mi], bf[ni][0], bf[ni][1]);
        }
    }
    __syncthreads();   // all warps done with last stage before red[] reuse

    // ---------------- fused epilogue ----------------
    const float INF = __int_as_float(0x7f800000);
    float rmin[2][2];

#pragma unroll
    for (int mi = 0; mi < 2; mi++)
#pragma unroll
        for (int h = 0; h < 2; h++) {
            int rloc = wm * 32 + mi * 16 + lr + 8 * h;
            float rm = INF;
#pragma unroll
            for (int ni = 0; ni < 8; ni++)
#pragma unroll
                for (int cc = 0; cc < 2; cc++) {
                    int cloc = wn * 64 + ni * 8 + lc * 2 + cc;
                    float e = c2s[cloc] - acc[mi][ni][h * 2 + cc];
                    int cg = n0 + cloc;
                    bool excl = (cg >= NCLS);
                    if (self) {
                        excl = excl || (cg == m0 + rloc);
                    } else if (cg == labs[rloc]) {
                        g_pos[m0 + rloc] = e;
                        excl = true;
                    }
                    if (!excl) rm = fminf(rm, e);
                }
            rmin[mi][h] = rm;
        }

#pragma unroll
    for (int mi = 0; mi < 2; mi++)
#pragma unroll
        for (int h = 0; h < 2; h++) {
            float v = rmin[mi][h];
            v = fminf(v, __shfl_xor_sync(0xffffffffu, v, 1));
            v = fminf(v, __shfl_xor_sync(0xffffffffu, v, 2));
            rmin[mi][h] = v;
        }

    if (lc == 0) {
#pragma unroll
        for (int mi = 0; mi < 2; mi++)
#pragma unroll
            for (int h = 0; h < 2; h++) {
                int rloc = wm * 32 + mi * 16 + lr + 8 * h;
                red[rloc * 2 + wn] = rmin[mi][h];
            }
    }
    __syncthreads();

    if (tid < 128) {
        float v = fminf(red[tid * 2], red[tid * 2 + 1]);
        int rg = m0 + tid;
        if (self) {
            if (rg < NCLS) g_mincc[(size_t)rg * NT + bx] = v;
        } else {
            g_minxc[(size_t)rg * NT + bx] = v;
        }
    }
}

// ---------------------------------------------------------------------------
// Deterministic reduction: 64 blocks; LAST block (ticket) does the final sum
// of the 64 partials in fixed order and resets the ticket for graph replays.
// ---------------------------------------------------------------------------
__global__ void partial_kernel(const int* __restrict__ labels, float* __restrict__ out) {
    int b = blockIdx.x * 256 + threadIdx.x;
    float4 a = reinterpret_cast<const float4*>(g_minxc)[b * 2];
    float4 c = reinterpret_cast<const float4*>(g_minxc)[b * 2 + 1];
    float m = fminf(fminf(fminf(a.x, a.y), fminf(a.z, a.w)),
                    fminf(fminf(c.x, c.y), fminf(c.z, c.w)));
    int lab = labels[b];
    float4 d = reinterpret_cast<const float4*>(g_mincc)[lab * 2];
    float4 e = reinterpret_cast<const float4*>(g_mincc)[lab * 2 + 1];
    float mc = fminf(fminf(fminf(d.x, d.y), fminf(d.z, d.w)),
                     fminf(fminf(e.x, e.y), fminf(e.z, e.w)));
    float t1 = g_pos[b] + 5.0f - m;              // 0.5||x||^2 cancels in pos - neg
    float t2 = 7.0f - (0.5f * g_c2[lab] + mc);   // cen fused
    float v = fmaxf(t1, 0.f) + fmaxf(t2, 0.f);
#pragma unroll
    for (int off = 16; off > 0; off >>= 1)
        v += __shfl_xor_sync(0xffffffffu, v, off);
    __shared__ float s[8];
    __shared__ bool last;
    if ((threadIdx.x & 31) == 0) s[threadIdx.x >> 5] = v;
    __syncthreads();
    if (threadIdx.x == 0) {
        float t = s[0];
#pragma unroll
        for (int w = 1; w < 8; w++) t += s[w];
        g_part[blockIdx.x] = t;
        __threadfence();                          // publish partial before ticket
        last = (atomicAdd(&g_ticket, 1) == 63);
    }
    __syncthreads();
    if (last && threadIdx.x == 0) {
        __threadfence();                          // acquire all partials
        float t = 0.f;
#pragma unroll
        for (int w = 0; w < 64; w++) t += g_part[w];   // fixed order: deterministic
        out[0] = t * (1.0f / (float)BATCH);
        g_ticket = 0;                              // reset for next graph replay
    }
}

// ---------------------------------------------------------------------------
// Launch
// ---------------------------------------------------------------------------
extern "C" void kernel_launch(void* const* d_in, const int* in_sizes, int n_in,
                              void* d_out, int out_size) {
    const float* x       = (const float*)d_in[0];
    const int*   labels  = (const int*)d_in[1];
    const float* centers = (const float*)d_in[2];
    float* out = (float*)d_out;

    const int smem_bytes = (NSTG * STG_U32 + 128 + 256 + 128) * 4;   // 112640
    cudaFuncSetAttribute(gemm_min_kernel,
                         cudaFuncAttributeMaxDynamicSharedMemorySize, smem_bytes);

    // fused prep: x conversion (blocks 0..2047, 8 float4/thread) + centers
    conv_all_kernel<<<XCONV_BLKS + NCLS, 256>>>(x, centers);

    // merged GEMM: x vs centers (grid.y < 128) + centers vs centers (grid.y >= 128)
    gemm_min_kernel<<<dim3(NT, GRIDY), 256, smem_bytes>>>(labels);

    // single reduction launch (finish fused via ticket)
    partial_kernel<<<64, 256>>>(labels, out);
}